// round 17
// baseline (speedup 1.0000x reference)
#include <cuda_runtime.h>
#include <cstdint>

// ============================================================================
// y[m,o] = fq_tok(x)[m,:] . fq_ch(w)[o,:] + b[o]
//   fq value = q * s, q integer in [-128,127]:
//   y[m,o] = sx[m]*sw[o]*(sum_k qx[m,k]*qw[o,k]) + b[o]
// Exact int8 GEMM. sm_103 family-PTX (tcgen05 rejected). Calibrated:
//   tensor pipe 64 MACs/SMSP/cyc; dp4a (fma pipe) 128 MACs/SMSP/cyc.
//   Tensor-pipe duty is pinned at ~70% in every role-split scheme (r6-r16):
//   role warps phase-lock (LDSM phases coincide) and the pipe drains.
// Round 17: FUSED ROLES + PHASE STAGGER. Every warp drives both pipes:
//   per warp: 16x64 MMA tile (rows 0-63) AND per thread a 4x8 dp4a tile
//   (rows 64-127). Even warps run MMA-block then dp4a-block; odd warps the
//   reverse -> at any time ~half the warps feed the tensor pipe, half issue
//   dp4a, filling each other's bubbles.
// BM=BN=128, BK=64, 4-stage cp.async, 80B rows, 256 threads, 2 CTAs/SM.
// M = 8192 (derived), N = 4096, K = 4096.
// ============================================================================

#define MAX_M 8192
#define NN 4096
#define KK 4096

__device__ int8_t g_qx[(size_t)MAX_M * KK];   // 32 MB
__device__ int8_t g_qw[(size_t)NN * KK];      // 16 MB
__device__ float g_sx[MAX_M];
__device__ float g_sw[NN];

// ---------------------------------------------------------------------------
// PTX helpers (family-portable, sm_80+ baseline ISA)
// ---------------------------------------------------------------------------
__device__ __forceinline__ uint32_t smem_u32(const void* p) {
    uint32_t a;
    asm("{ .reg .u64 t; cvta.to.shared.u64 t, %1; cvt.u32.u64 %0, t; }" : "=r"(a) : "l"(p));
    return a;
}

#define CP_ASYNC16(smem, gptr) \
    asm volatile("cp.async.cg.shared.global [%0], [%1], 16;" \
        :: "r"((uint32_t)(smem)), "l"(gptr) : "memory")
#define CP_COMMIT() asm volatile("cp.async.commit_group;" ::: "memory")
#define CP_WAIT(n)  asm volatile("cp.async.wait_group %0;" :: "n"(n) : "memory")

#define LDSM_X4(r0, r1, r2, r3, addr) \
    asm volatile("ldmatrix.sync.aligned.m8n8.x4.shared.b16 {%0,%1,%2,%3}, [%4];" \
        : "=r"(r0), "=r"(r1), "=r"(r2), "=r"(r3) : "r"((uint32_t)(addr)))

#define MMA_S8(d, a0, a1, a2, a3, b0, b1) \
    asm volatile("mma.sync.aligned.m16n8k32.row.col.s32.s8.s8.s32 " \
        "{%0,%1,%2,%3},{%4,%5,%6,%7},{%8,%9},{%0,%1,%2,%3};" \
        : "+r"((d)[0]), "+r"((d)[1]), "+r"((d)[2]), "+r"((d)[3]) \
        : "r"(a0), "r"(a1), "r"(a2), "r"(a3), "r"(b0), "r"(b1))

// ---------------------------------------------------------------------------
// Kernel 1: fused per-row symmetric fake-quant for BOTH x and w -> int8+scale.
// ---------------------------------------------------------------------------
__global__ __launch_bounds__(256) void quant_rows(const float* __restrict__ x,
                                                  const float* __restrict__ w,
                                                  int M) {
    const int bid = blockIdx.x;
    const bool is_x = bid < M;
    const int row = is_x ? bid : bid - M;
    const float* in = is_x ? x : w;
    int8_t* qout = is_x ? g_qx : g_qw;
    float* sout = is_x ? g_sx : g_sw;

    const int t = threadIdx.x;
    const float4* src = reinterpret_cast<const float4*>(in) + (size_t)row * (KK / 4);

    float4 v[4];
    float am = 0.f;
#pragma unroll
    for (int j = 0; j < 4; j++) {
        v[j] = src[t + j * 256];
        am = fmaxf(am, fmaxf(fmaxf(fabsf(v[j].x), fabsf(v[j].y)),
                             fmaxf(fabsf(v[j].z), fabsf(v[j].w))));
    }
#pragma unroll
    for (int o = 16; o; o >>= 1) am = fmaxf(am, __shfl_xor_sync(0xffffffffu, am, o));

    __shared__ float s_red[8];
    __shared__ float s_scale;
    if ((t & 31) == 0) s_red[t >> 5] = am;
    __syncthreads();
    if (t < 8) {
        float a = s_red[t];
#pragma unroll
        for (int o = 4; o; o >>= 1) a = fmaxf(a, __shfl_xor_sync(0xffu, a, o));
        if (t == 0) {
            float sc = fmaxf(a / 127.0f, 1e-8f);
            s_scale = sc;
            sout[row] = sc;
        }
    }
    __syncthreads();
    const float inv = 1.0f / s_scale;

    uint32_t* qrow = reinterpret_cast<uint32_t*>(qout + (size_t)row * KK);
#pragma unroll
    for (int j = 0; j < 4; j++) {
        int q0 = min(max(__float2int_rn(v[j].x * inv), -128), 127);
        int q1 = min(max(__float2int_rn(v[j].y * inv), -128), 127);
        int q2 = min(max(__float2int_rn(v[j].z * inv), -128), 127);
        int q3 = min(max(__float2int_rn(v[j].w * inv), -128), 127);
        qrow[t + j * 256] = (uint32_t)(q0 & 0xff) | ((uint32_t)(q1 & 0xff) << 8) |
                            ((uint32_t)(q2 & 0xff) << 16) | ((uint32_t)q3 << 24);
    }
}

// ---------------------------------------------------------------------------
// Kernel 2: fused-role hybrid int8 GEMM. BM=BN=128, BK=64, 4-stage cp.async,
// 80B-padded smem rows, 256 threads, 2 CTAs/SM.
// Every warp: MMA tile 16x64 (rows (wid&3)*16, cols (wid>>2)*64) + per-thread
// dp4a tile 4x8 (rows 64 + (t>>4)*4, cols {(t&15)+16c}).
// Even warps: MMA then dp4a; odd warps: dp4a then MMA (phase stagger).
// ---------------------------------------------------------------------------
#define STAGES 4
#define STAGE_BYTES (2 * 128 * 80)

__global__ __launch_bounds__(256, 2) void gemm_fused(const float* __restrict__ bias,
                                                     float* __restrict__ out) {
    constexpr int KT = KK / 64;   // 64 main-loop iterations

    extern __shared__ char sm[];
    __shared__ float s_sw[128];
    __shared__ float s_bias[128];

    const int t = threadIdx.x;
    const int bid = blockIdx.x;
    const int mt = bid >> 5;
    const int nt = bid & 31;
    const int m0 = mt * 128;
    const int n0 = nt * 128;

    if (t < 128) {
        s_sw[t] = g_sw[n0 + t];
        s_bias[t] = bias[n0 + t];
    }

    const int8_t* gA = g_qx + (size_t)m0 * KK;
    const int8_t* gB = g_qw + (size_t)n0 * KK;
    const uint32_t smbase = smem_u32(sm);

    // cp.async mapping: 512 16B chunks per tile, 2 per thread per tile.
    const int crow = t >> 2;
    const int ccol = t & 3;

    auto issue = [&](int it) {
        const int s = it % STAGES;
        const uint32_t sa = smbase + s * STAGE_BYTES;
        const uint32_t sb = sa + 128 * 80;
        const int koff = it * 64 + ccol * 16;
#pragma unroll
        for (int j = 0; j < 2; j++) {
            const int r = crow + j * 64;
            const uint32_t so = (uint32_t)r * 80u + (uint32_t)ccol * 16u;
            CP_ASYNC16(sa + so, gA + (size_t)r * KK + koff);
            CP_ASYNC16(sb + so, gB + (size_t)r * KK + koff);
        }
    };

#pragma unroll
    for (int it = 0; it < STAGES - 1; ++it) {
        issue(it);
        CP_COMMIT();
    }

    const int wid = t >> 5;
    const int lane = t & 31;
    const int warpM = wid & 3;    // MMA rows warpM*16..+15
    const int warpN = wid >> 2;   // MMA cols warpN*64..+63
    const int tr = t >> 4;        // dp4a rows 64 + tr*4..+3  (tr 0..15)
    const int tc = t & 15;        // dp4a cols {tc + 16c, c<8}

    // MMA fragment offsets (within a stage)
    const uint32_t a_off =
        (uint32_t)(warpM * 16 + (lane & 15)) * 80u + (uint32_t)(lane >> 4) * 16u;
    const uint32_t b_off = 128u * 80u +
        (uint32_t)(warpN * 64 + (lane & 7) + ((lane >> 4) & 1) * 8) * 80u +
        (uint32_t)((lane >> 3) & 1) * 16u;

    // dp4a offsets (within a stage)
    const uint32_t da_base = (uint32_t)(64 + tr * 4) * 80u;
    const uint32_t db_base = 128u * 80u + (uint32_t)tc * 80u;

    int amm[8][4];                // MMA acc: 8 n8-tiles x 4
#pragma unroll
    for (int b = 0; b < 8; b++)
#pragma unroll
        for (int i = 0; i < 4; i++) amm[b][i] = 0;

    int adp[4][8];                // dp4a acc: 4 rows x 8 cols
#pragma unroll
    for (int r = 0; r < 4; r++)
#pragma unroll
        for (int c = 0; c < 8; c++) adp[r][c] = 0;

    // Per-iteration compute blocks -------------------------------------------
    auto mma_block = [&](uint32_t base) {
#pragma unroll
        for (int s = 0; s < 2; ++s) {
            uint32_t a0, a1, a2, a3;
            LDSM_X4(a0, a1, a2, a3, base + a_off + (uint32_t)s * 32u);
#pragma unroll
            for (int np = 0; np < 4; np++) {
                uint32_t b0, b1, b2, b3;
                LDSM_X4(b0, b1, b2, b3,
                        base + b_off + (uint32_t)np * (16u * 80u) + (uint32_t)s * 32u);
                MMA_S8(amm[2 * np + 0], a0, a1, a2, a3, b0, b1);
                MMA_S8(amm[2 * np + 1], a0, a1, a2, a3, b2, b3);
            }
        }
    };

    auto dp4a_block = [&](uint32_t base) {
#pragma unroll
        for (int g = 0; g < 4; g++) {      // 4 groups of 16 K-bytes
            const uint32_t go = (uint32_t)g * 16u;
            uint4 a4[4];
#pragma unroll
            for (int r = 0; r < 4; r++) {
                a4[r] = *reinterpret_cast<const uint4*>(
                    sm + (base - smbase) + da_base + (uint32_t)r * 80u + go);
            }
#pragma unroll
            for (int c = 0; c < 8; c++) {
                const uint4 bv = *reinterpret_cast<const uint4*>(
                    sm + (base - smbase) + db_base + (uint32_t)c * (16u * 80u) + go);
#pragma unroll
                for (int r = 0; r < 4; r++) {
                    int v = __dp4a((int)a4[r].x, (int)bv.x, adp[r][c]);
                    v = __dp4a((int)a4[r].y, (int)bv.y, v);
                    v = __dp4a((int)a4[r].z, (int)bv.z, v);
                    adp[r][c] = __dp4a((int)a4[r].w, (int)bv.w, v);
                }
            }
        }
    };

    const bool mma_first = (wid & 1) == 0;

    for (int it = 0; it < KT; ++it) {
        CP_WAIT(STAGES - 2);
        __syncthreads();
        const int nit = it + STAGES - 1;
        if (nit < KT) issue(nit);
        CP_COMMIT();

        const uint32_t base = smbase + (uint32_t)(it % STAGES) * STAGE_BYTES;

        if (mma_first) {
            mma_block(base);
            dp4a_block(base);
        } else {
            dp4a_block(base);
            mma_block(base);
        }
    }

    // ===== Epilogues =========================================================
    // MMA part: rows warpM*16..+15, cols warpN*64..+63.
    {
        const int r0 = m0 + warpM * 16 + (lane >> 2);
        const float sx0 = g_sx[r0];
        const float sx1 = g_sx[r0 + 8];
        float* o0 = out + (size_t)r0 * NN + n0;
        float* o1 = o0 + (size_t)8 * NN;
#pragma unroll
        for (int ntl = 0; ntl < 8; ntl++) {
            const int lc = warpN * 64 + ntl * 8 + (lane & 3) * 2;
            const float w0 = s_sw[lc], w1 = s_sw[lc + 1];
            const float bb0 = s_bias[lc], bb1 = s_bias[lc + 1];
            float2 v0, v1;
            v0.x = fmaf((float)amm[ntl][0] * sx0, w0, bb0);
            v0.y = fmaf((float)amm[ntl][1] * sx0, w1, bb1);
            v1.x = fmaf((float)amm[ntl][2] * sx1, w0, bb0);
            v1.y = fmaf((float)amm[ntl][3] * sx1, w1, bb1);
            *reinterpret_cast<float2*>(o0 + lc) = v0;
            *reinterpret_cast<float2*>(o1 + lc) = v1;
        }
    }
    // dp4a part: rows m0+64+tr*4..+3, cols {tc+16c}.
#pragma unroll
    for (int r = 0; r < 4; r++) {
        const int row = m0 + 64 + tr * 4 + r;
        const float sxv = g_sx[row];
        float* orow = out + (size_t)row * NN + n0;
#pragma unroll
        for (int c = 0; c < 8; c++) {
            const int lc = tc + 16 * c;
            orow[lc] = fmaf((float)adp[r][c] * sxv, s_sw[lc], s_bias[lc]);
        }
    }
}

// ---------------------------------------------------------------------------
// Launch
// ---------------------------------------------------------------------------
extern "C" void kernel_launch(void* const* d_in, const int* in_sizes, int n_in,
                              void* d_out, int out_size) {
    const float* x = (const float*)d_in[0];   // [M, 4096]
    const float* w = (const float*)d_in[1];   // [4096, 4096]
    const float* b = (const float*)d_in[2];   // [4096]
    float* out = (float*)d_out;               // [M, 4096]

    const int M = in_sizes[0] / KK;           // 8192

    quant_rows<<<M + NN, 256>>>(x, w, M);

    cudaFuncSetAttribute(gemm_fused, cudaFuncAttributeMaxDynamicSharedMemorySize,
                         STAGES * STAGE_BYTES);

    const int total_tiles = (M / 128) * (NN / 128);   // 2048
    gemm_fused<<<total_tiles, 256, STAGES * STAGE_BYTES>>>(b, out);
}